// round 16
// baseline (speedup 1.0000x reference)
#include <cuda_runtime.h>
#include <cuda_fp16.h>
#include <math.h>
#include <stdint.h>

#define BATCH 16
#define NSEQ 4096
#define CDIM 512
#define MTOT (BATCH * NSEQ)
#define ELEMS ((size_t)BATCH * CDIM * NSEQ)

__device__ __half g_Qh[ELEMS];
__device__ __half g_Kh[ELEMS];
__device__ __half g_Vh[ELEMS];
__device__ __half g_Oh[ELEMS];

__device__ __half g_xh[(size_t)MTOT * CDIM];
__device__ __half g_wh[3 * CDIM * CDIM];

__device__ __forceinline__ uint32_t smem_u32(const void* p) {
    uint32_t a;
    asm("{ .reg .u64 t; cvta.to.shared.u64 t, %1; cvt.u32.u64 %0, t; }"
        : "=r"(a) : "l"(p));
    return a;
}

#define LDSM_X4(r0, r1, r2, r3, addr) \
    asm volatile("ldmatrix.sync.aligned.m8n8.x4.shared.b16 {%0,%1,%2,%3}, [%4];" \
        : "=r"(r0), "=r"(r1), "=r"(r2), "=r"(r3) : "r"(addr))

#define LDSM_X4T(r0, r1, r2, r3, addr) \
    asm volatile("ldmatrix.sync.aligned.m8n8.x4.trans.shared.b16 {%0,%1,%2,%3}, [%4];" \
        : "=r"(r0), "=r"(r1), "=r"(r2), "=r"(r3) : "r"(addr))

#define MMA_F16(c, a0, a1, a2, a3, b0, b1) \
    asm volatile("mma.sync.aligned.m16n8k16.row.col.f32.f16.f16.f32 " \
        "{%0,%1,%2,%3}, {%4,%5,%6,%7}, {%8,%9}, {%0,%1,%2,%3};" \
        : "+f"((c)[0]), "+f"((c)[1]), "+f"((c)[2]), "+f"((c)[3]) \
        : "r"(a0), "r"(a1), "r"(a2), "r"(a3), "r"(b0), "r"(b1))

#define CP_ASYNC16(dst, src) \
    asm volatile("cp.async.cg.shared.global [%0], [%1], 16;" \
        :: "r"(dst), "l"(src) : "memory")

// ---------------------------------------------------------------------------
// fp32 -> fp16 conversion kernels
// ---------------------------------------------------------------------------
__global__ __launch_bounds__(256) void convX_kernel(
    const float4* __restrict__ in, uint2* __restrict__ outp, int n4)
{
    int i = blockIdx.x * 512 + threadIdx.x;
    #pragma unroll
    for (int r = 0; r < 2; ++r) {
        int idx = i + r * 256;
        if (idx < n4) {
            float4 v = in[idx];
            __half2 h0 = __floats2half2_rn(v.x, v.y);
            __half2 h1 = __floats2half2_rn(v.z, v.w);
            uint2 o;
            o.x = *(uint32_t*)&h0;
            o.y = *(uint32_t*)&h1;
            outp[idx] = o;
        }
    }
}

__global__ __launch_bounds__(256) void convW_kernel(
    const float4* __restrict__ Wq,
    const float4* __restrict__ Wk,
    const float4* __restrict__ Wv,
    uint2* __restrict__ outp)
{
    const int z = blockIdx.y;
    const float4* src = (z == 0) ? Wq : (z == 1) ? Wk : Wv;
    const int n4 = CDIM * CDIM / 4;
    int i = blockIdx.x * 256 + threadIdx.x;
    if (i >= n4) return;
    float4 v = src[i];
    __half2 h0 = __floats2half2_rn(v.x, v.y);
    __half2 h1 = __floats2half2_rn(v.z, v.w);
    uint2 o;
    o.x = *(uint32_t*)&h0;
    o.y = *(uint32_t*)&h1;
    outp[(size_t)z * n4 + i] = o;
}

// ---------------------------------------------------------------------------
// Projection GEMM via mma.sync (fp16, fp32 accum).
// K32 chunks, 5-stage cp.async ring, wait_group 3 (3 groups in flight),
// 2 CTA/SM, L2-friendly grid, d-half split.
// ---------------------------------------------------------------------------
#define PTS 40
#define PTILE_B (128 * PTS * 2)
#define PSTAGE_B (2 * PTILE_B)        // 20480
#define PROJ_SMEM (5 * PSTAGE_B)      // 102400

__global__ __launch_bounds__(256, 2) void proj_mma_kernel(
    const __half* __restrict__ xh,
    const __half* __restrict__ whp,
    const float* __restrict__ biasq,
    const float* __restrict__ biask,
    const float* __restrict__ biasv,
    int d_base)
{
    extern __shared__ __half smem[];
    const uint32_t smb = smem_u32(smem);

    const int tid  = threadIdx.x;
    const int lane = tid & 31;
    const int warp = tid >> 5;
    const int wm   = warp >> 2;
    const int wn   = warp & 3;

    const int bx = blockIdx.x;              // 0..5
    const int z  = bx >> 1;
    const int d0 = ((bx & 1) + d_base) * 128;
    const int n0 = blockIdx.y * 128;

    const __half* W = whp + (size_t)z * CDIM * CDIM;

    float acc[4][4][4];
    #pragma unroll
    for (int i = 0; i < 4; ++i)
        #pragma unroll
        for (int j = 0; j < 4; ++j)
            #pragma unroll
            for (int q = 0; q < 4; ++q) acc[i][j][q] = 0.f;

    const int lr = tid >> 1;
    const int lc = (tid & 1) * 16;

    #define LOAD_STAGE(s, k0) do { \
        const uint32_t db = smb + (s) * PSTAGE_B + (uint32_t)(lr * PTS + lc) * 2; \
        const size_t go = (size_t)lr * 512 + (k0) + lc; \
        CP_ASYNC16(db,                W + (size_t)d0 * 512 + go); \
        CP_ASYNC16(db + 16,           W + (size_t)d0 * 512 + go + 8); \
        CP_ASYNC16(db + PTILE_B,      xh + (size_t)n0 * 512 + go); \
        CP_ASYNC16(db + PTILE_B + 16, xh + (size_t)n0 * 512 + go + 8); \
        asm volatile("cp.async.commit_group;" ::: "memory"); \
    } while (0)

    LOAD_STAGE(0, 0);
    LOAD_STAGE(1, 32);
    LOAD_STAGE(2, 64);
    LOAD_STAGE(3, 96);

    const int aRow  = wm * 64 + (lane & 15);
    const int aCol  = (lane >> 4) * 8;
    const int g     = lane >> 3;
    const int bRow  = wn * 32 + (g & 2) * 4 + (lane & 7);
    const int bElem = (g & 1) * 8;

    int slot = 0;
    for (int kt = 0; kt < 16; ++kt) {
        if (kt >= 12) {
            asm volatile("cp.async.wait_group %0;" :: "n"(0) : "memory");
        } else {
            asm volatile("cp.async.wait_group %0;" :: "n"(3) : "memory");
        }
        __syncthreads();

        // prefetch stage kt+4 into slot (kt+4)%5 = slot consumed at kt-1
        if (kt < 12) {
            int ns = slot + 4; if (ns >= 5) ns -= 5;
            LOAD_STAGE(ns, (kt + 4) * 32);
        }

        const uint32_t sA = smb + slot * PSTAGE_B;
        const uint32_t sB = sA + PTILE_B;

        #pragma unroll
        for (int kk = 0; kk < 2; ++kk) {
            uint32_t bh[4][2];
            #pragma unroll
            for (int p = 0; p < 2; ++p) {
                uint32_t ba = sB + (uint32_t)((bRow + p * 16) * PTS + kk * 16 + bElem) * 2;
                LDSM_X4(bh[2 * p][0], bh[2 * p][1], bh[2 * p + 1][0], bh[2 * p + 1][1], ba);
            }
            #pragma unroll
            for (int mi = 0; mi < 4; ++mi) {
                uint32_t aa = sA + (uint32_t)((aRow + mi * 16) * PTS + kk * 16 + aCol) * 2;
                uint32_t a0, a1, a2, a3;
                LDSM_X4(a0, a1, a2, a3, aa);
                #pragma unroll
                for (int ni = 0; ni < 4; ++ni)
                    MMA_F16(acc[mi][ni], a0, a1, a2, a3, bh[ni][0], bh[ni][1]);
            }
        }
        if (++slot == 5) slot = 0;
    }

    const float* bias = (z == 0) ? biasq : (z == 1) ? biask : biasv;
    __half* outp = (z == 0) ? g_Qh : (z == 1) ? g_Kh : g_Vh;
    const int b  = n0 >> 12;
    const int nb = (n0 & 4095) + wn * 32 + (lane & 3) * 2;

    #pragma unroll
    for (int mi = 0; mi < 4; ++mi) {
        const int dA = d0 + wm * 64 + mi * 16 + (lane >> 2);
        const float bA = bias[dA];
        const float bB = bias[dA + 8];
        __half* rowA = outp + (((size_t)(b * 512 + dA)) << 12) + nb;
        __half* rowB = rowA + ((size_t)8 << 12);
        #pragma unroll
        for (int ni = 0; ni < 4; ++ni) {
            float s0 = 1.f / (1.f + __expf(-(acc[mi][ni][0] + bA)));
            float s1 = 1.f / (1.f + __expf(-(acc[mi][ni][1] + bA)));
            float s2 = 1.f / (1.f + __expf(-(acc[mi][ni][2] + bB)));
            float s3 = 1.f / (1.f + __expf(-(acc[mi][ni][3] + bB)));
            *(__half2*)(rowA + ni * 8) = __floats2half2_rn(s0, s1);
            *(__half2*)(rowB + ni * 8) = __floats2half2_rn(s2, s3);
        }
    }
}

// ---------------------------------------------------------------------------
// Attention via fp16 tensor cores. Aliased smem (55296 B, 4 CTA/SM). c-half split.
// ---------------------------------------------------------------------------
#define SH72 72
#define SH40 40
#define SF36 36
#define SF68 68

#define OFF_HQ   0
#define OFF_HK   9216
#define OFF_HV   18432
#define OFF_Hq   27648
#define OFF_Hk   32256
#define OFF_HQK  27648
#define OFF_HKQ  32768
#define OFF_S1   37376
#define OFF_S2   46592
#define OFF_HKQV 37376
#define ATT_SMEM_BYTES 55296

__global__ __launch_bounds__(256) void attn_kernel(
    const __half* __restrict__ gQ,
    const __half* __restrict__ gK,
    const __half* __restrict__ gV,
    __half* __restrict__ gO,
    int c_base)
{
    extern __shared__ char sm8[];
    const uint32_t sb = smem_u32(sm8);
    __half* hQ   = (__half*)(sm8 + OFF_HQ);
    __half* hK   = (__half*)(sm8 + OFF_HK);
    __half* hq   = (__half*)(sm8 + OFF_Hq);
    __half* hk   = (__half*)(sm8 + OFF_Hk);
    __half* hQk  = (__half*)(sm8 + OFF_HQK);
    __half* hKq  = (__half*)(sm8 + OFF_HKQ);
    __half* hKqv = (__half*)(sm8 + OFF_HKQV);
    float*  sS1  = (float*)(sm8 + OFF_S1);
    float*  sS2  = (float*)(sm8 + OFF_S2);

    const int bc = blockIdx.y * 512 + c_base + blockIdx.x;
    const size_t base = (size_t)bc * 4096;
    const int tid  = threadIdx.x;
    const int lane = tid & 31;
    const int warp = tid >> 5;

    #pragma unroll
    for (int it = 0; it < 6; ++it) {
        int idx = tid + it * 256;
        int m    = idx >> 9;
        int rest = idx & 511;
        int r    = rest >> 3;
        int c8   = (rest & 7) * 8;
        const __half* src = (m == 0) ? gQ : (m == 1) ? gK : gV;
        uint4 v = *(const uint4*)(src + base + (r << 6) + c8);
        __half* dst = (__half*)(sm8 + (m == 0 ? OFF_HQ : m == 1 ? OFF_HK : OFF_HV)) + r * SH72 + c8;
        *(uint4*)dst = v;
    }
    __syncthreads();

    {
        const __half2 hhalf = __float2half2_rn(0.5f);
        #pragma unroll
        for (int it = 0; it < 8; ++it) {
            int idx = tid + it * 256;
            int which = idx >> 10;
            int i  = (idx >> 5) & 31;
            int cc = (idx & 31) * 2;
            const __half* s = which ? hK : hQ;
            __half* d      = which ? hk : hq;
            __half2 a = *(const __half2*)(s + (2 * i) * SH72 + cc);
            __half2 b = *(const __half2*)(s + (2 * i + 1) * SH72 + cc);
            *(__half2*)(d + i * SH72 + cc) = __hmul2(__hadd2(a, b), hhalf);
        }
    }
    __syncthreads();

    const float scale = 0.044194173824159216f;
    const int aRow = lane & 15;
    const int aCol = (lane >> 4) * 8;
    const int g    = lane >> 3;
    const int bR   = (g & 2) * 4 + (lane & 7);
    const int bE   = (g & 1) * 8;
    const int tR   = (g & 1) * 8 + (lane & 7);
    const int tC   = (g >> 1) * 8;
    const int cr   = lane >> 2;
    const int ccol = (lane & 3) * 2;

    {
        const int wm = warp >> 1, wn = warp & 1;
        float acc[2][4] = {{0,0,0,0},{0,0,0,0}};
        #pragma unroll
        for (int ks = 0; ks < 4; ++ks) {
            uint32_t a0,a1,a2,a3,b0,b1,b2,b3;
            LDSM_X4(a0,a1,a2,a3, sb + OFF_HQ + (uint32_t)((wm*16 + aRow)*SH72 + ks*16 + aCol)*2);
            LDSM_X4(b0,b1,b2,b3, sb + OFF_Hk + (uint32_t)((wn*16 + bR)*SH72 + ks*16 + bE)*2);
            MMA_F16(acc[0], a0,a1,a2,a3, b0,b1);
            MMA_F16(acc[1], a0,a1,a2,a3, b2,b3);
        }
        #pragma unroll
        for (int nt = 0; nt < 2; ++nt) {
            float* p0 = sS1 + (wm*16 + cr) * SF36 + wn*16 + nt*8 + ccol;
            float* p1 = p0 + 8 * SF36;
            *(float2*)p0 = make_float2(acc[nt][0]*scale, acc[nt][1]*scale);
            *(float2*)p1 = make_float2(acc[nt][2]*scale, acc[nt][3]*scale);
        }
    }

    {
        const int wm = warp >> 2, wn = warp & 3;
        float acc[2][4] = {{0,0,0,0},{0,0,0,0}};
        #pragma unroll
        for (int ks = 0; ks < 4; ++ks) {
            uint32_t a0,a1,a2,a3,b0,b1,b2,b3;
            LDSM_X4(a0,a1,a2,a3, sb + OFF_Hq + (uint32_t)((wm*16 + aRow)*SH72 + ks*16 + aCol)*2);
            LDSM_X4(b0,b1,b2,b3, sb + OFF_HK + (uint32_t)((wn*16 + bR)*SH72 + ks*16 + bE)*2);
            MMA_F16(acc[0], a0,a1,a2,a3, b0,b1);
            MMA_F16(acc[1], a0,a1,a2,a3, b2,b3);
        }
        #pragma unroll
        for (int nt = 0; nt < 2; ++nt) {
            float* p0 = sS2 + (wm*16 + cr) * SF68 + wn*16 + nt*8 + ccol;
            float* p1 = p0 + 8 * SF68;
            *(float2*)p0 = make_float2(acc[nt][0]*scale, acc[nt][1]*scale);
            *(float2*)p1 = make_float2(acc[nt][2]*scale, acc[nt][3]*scale);
        }
    }
    __syncthreads();

    {
        const int row = tid >> 2;
        const int s   = tid & 3;
        float* rp = sS1 + row * SF36 + s * 8;
        float4 v0 = *(float4*)rp;
        float4 v1 = *(float4*)(rp + 4);
        float m = fmaxf(fmaxf(fmaxf(v0.x, v0.y), fmaxf(v0.z, v0.w)),
                        fmaxf(fmaxf(v1.x, v1.y), fmaxf(v1.z, v1.w)));
        m = fmaxf(m, __shfl_xor_sync(0xffffffffu, m, 1));
        m = fmaxf(m, __shfl_xor_sync(0xffffffffu, m, 2));
        v0.x = __expf(v0.x - m); v0.y = __expf(v0.y - m);
        v0.z = __expf(v0.z - m); v0.w = __expf(v0.w - m);
        v1.x = __expf(v1.x - m); v1.y = __expf(v1.y - m);
        v1.z = __expf(v1.z - m); v1.w = __expf(v1.w - m);
        float su = v0.x + v0.y + v0.z + v0.w + v1.x + v1.y + v1.z + v1.w;
        su += __shfl_xor_sync(0xffffffffu, su, 1);
        su += __shfl_xor_sync(0xffffffffu, su, 2);
        float inv = 1.f / su;
        __half* wp = hQk + row * SH40 + s * 8;
        *(__half2*)(wp)     = __floats2half2_rn(v0.x * inv, v0.y * inv);
        *(__half2*)(wp + 2) = __floats2half2_rn(v0.z * inv, v0.w * inv);
        *(__half2*)(wp + 4) = __floats2half2_rn(v1.x * inv, v1.y * inv);
        *(__half2*)(wp + 6) = __floats2half2_rn(v1.z * inv, v1.w * inv);
    }

    {
        const int row = tid >> 3;
        const int s   = tid & 7;
        float* rp = sS2 + row * SF68 + s * 8;
        float4 v0 = *(float4*)rp;
        float4 v1 = *(float4*)(rp + 4);
        float m = fmaxf(fmaxf(fmaxf(v0.x, v0.y), fmaxf(v0.z, v0.w)),
                        fmaxf(fmaxf(v1.x, v1.y), fmaxf(v1.z, v1.w)));
        m = fmaxf(m, __shfl_xor_sync(0xffffffffu, m, 1));
        m = fmaxf(m, __shfl_xor_sync(0xffffffffu, m, 2));
        m = fmaxf(m, __shfl_xor_sync(0xffffffffu, m, 4));
        v0.x = __expf(v0.x - m); v0.y = __expf(v0.y - m);
        v0.z = __expf(v0.z - m); v0.w = __expf(v0.w - m);
        v1.x = __expf(v1.x - m); v1.y = __expf(v1.y - m);
        v1.z = __expf(v1.z - m); v1.w = __expf(v1.w - m);
        float su = v0.x + v0.y + v0.z + v0.w + v1.x + v1.y + v1.z + v1.w;
        su += __shfl_xor_sync(0xffffffffu, su, 1);
        su += __shfl_xor_sync(0xffffffffu, su, 2);
        su += __shfl_xor_sync(0xffffffffu, su, 4);
        float inv = 1.f / su;
        __half* wp = hKq + row * SH72 + s * 8;
        *(__half2*)(wp)     = __floats2half2_rn(v0.x * inv, v0.y * inv);
        *(__half2*)(wp + 2) = __floats2half2_rn(v0.z * inv, v0.w * inv);
        *(__half2*)(wp + 4) = __floats2half2_rn(v1.x * inv, v1.y * inv);
        *(__half2*)(wp + 6) = __floats2half2_rn(v1.z * inv, v1.w * inv);
    }
    __syncthreads();

    {
        const int wm = warp >> 2, wn = warp & 3;
        float acc[2][4] = {{0,0,0,0},{0,0,0,0}};
        #pragma unroll
        for (int ks = 0; ks < 4; ++ks) {
            uint32_t a0,a1,a2,a3,b0,b1,b2,b3;
            LDSM_X4(a0,a1,a2,a3, sb + OFF_HKQ + (uint32_t)((wm*16 + aRow)*SH72 + ks*16 + aCol)*2);
            LDSM_X4T(b0,b1,b2,b3, sb + OFF_HV + (uint32_t)((ks*16 + tR)*SH72 + wn*16 + tC)*2);
            MMA_F16(acc[0], a0,a1,a2,a3, b0,b1);
            MMA_F16(acc[1], a0,a1,a2,a3, b2,b3);
        }
        #pragma unroll
        for (int nt = 0; nt < 2; ++nt) {
            __half* p0 = hKqv + (wm*16 + cr) * SH72 + wn*16 + nt*8 + ccol;
            __half* p1 = p0 + 8 * SH72;
            *(__half2*)p0 = __floats2half2_rn(acc[nt][0], acc[nt][1]);
            *(__half2*)p1 = __floats2half2_rn(acc[nt][2], acc[nt][3]);
        }
    }
    __syncthreads();

    {
        const int wm = warp >> 1, wn = warp & 1;
        float acc[4][4];
        #pragma unroll
        for (int i = 0; i < 4; ++i)
            #pragma unroll
            for (int q = 0; q < 4; ++q) acc[i][q] = 0.f;
        #pragma unroll
        for (int ks = 0; ks < 2; ++ks) {
            uint32_t a0,a1,a2,a3;
            LDSM_X4(a0,a1,a2,a3, sb + OFF_HQK + (uint32_t)((wm*16 + aRow)*SH40 + ks*16 + aCol)*2);
            #pragma unroll
            for (int nh = 0; nh < 2; ++nh) {
                uint32_t b0,b1,b2,b3;
                LDSM_X4T(b0,b1,b2,b3,
                    sb + OFF_HKQV + (uint32_t)((ks*16 + tR)*SH72 + wn*32 + nh*16 + tC)*2);
                MMA_F16(acc[nh*2+0], a0,a1,a2,a3, b0,b1);
                MMA_F16(acc[nh*2+1], a0,a1,a2,a3, b2,b3);
            }
        }
        #pragma unroll
        for (int nt = 0; nt < 4; ++nt) {
            __half* p0 = gO + base + (wm*16 + cr) * 64 + wn*32 + nt*8 + ccol;
            __half* p1 = p0 + 8 * 64;
            *(__half2*)p0 = __floats2half2_rn(acc[nt][0], acc[nt][1]);
            *(__half2*)p1 = __floats2half2_rn(acc[nt][2], acc[nt][3]);
        }
    }
}

// ---------------------------------------------------------------------------
// Transpose [B][C][N] fp16 -> [B][N][C] fp32, split by c-half (c_tile_base).
// ---------------------------------------------------------------------------
__global__ __launch_bounds__(256) void transpose_kernel(
    const __half* __restrict__ gO, float* __restrict__ out, int c_tile_base)
{
    __shared__ float tile[64][33];
    const int b  = blockIdx.z;
    const int n0 = blockIdx.x * 64;
    const int c0 = (blockIdx.y + c_tile_base) * 32;
    const int tx = threadIdx.x;
    const int ty = threadIdx.y;
    const int tid = ty * 8 + tx;

    const __half* src = gO + ((size_t)b * 512 + c0 + ty) * 4096 + n0 + tx * 8;
    uint4 v = *(const uint4*)src;
    const __half* hv = (const __half*)&v;
    #pragma unroll
    for (int e = 0; e < 8; ++e)
        tile[tx * 8 + e][ty] = __half2float(hv[e]);
    __syncthreads();

    float* dst = out + ((size_t)b * 4096) * 512;
    #pragma unroll
    for (int k = 0; k < 8; ++k) {
        int lin = tid + k * 256;
        int n = lin >> 5;
        int c = lin & 31;
        dst[(size_t)(n0 + n) * 512 + c0 + c] = tile[n][c];
    }
}

// ---------------------------------------------------------------------------
// Host side — 3-deep fork/join pipeline:
//   projA -> (projB || attnA) -> (attnB || transposeA) -> transposeB
// ---------------------------------------------------------------------------
extern "C" void kernel_launch(void* const* d_in, const int* in_sizes, int n_in,
                              void* d_out, int out_size)
{
    (void)in_sizes; (void)n_in; (void)out_size;
    const float* x  = (const float*)d_in[0];
    const float* Wq = (const float*)d_in[1];
    const float* bq = (const float*)d_in[2];
    const float* Wk = (const float*)d_in[3];
    const float* bk = (const float*)d_in[4];
    const float* Wv = (const float*)d_in[5];
    const float* bv = (const float*)d_in[6];
    float* out = (float*)d_out;

    __half *pQ, *pK, *pV, *pO, *pxh, *pwh;
    cudaGetSymbolAddress((void**)&pQ, g_Qh);
    cudaGetSymbolAddress((void**)&pK, g_Kh);
    cudaGetSymbolAddress((void**)&pV, g_Vh);
    cudaGetSymbolAddress((void**)&pO, g_Oh);
    cudaGetSymbolAddress((void**)&pxh, g_xh);
    cudaGetSymbolAddress((void**)&pwh, g_wh);

    static cudaStream_t s2 = nullptr;
    static cudaEvent_t evA = nullptr, evB = nullptr, evC = nullptr, evD = nullptr;
    static bool tried = false;
    if (!tried) {
        tried = true;
        if (cudaStreamCreateWithFlags(&s2, cudaStreamNonBlocking) != cudaSuccess)
            s2 = nullptr;
        if (s2) {
            if (cudaEventCreateWithFlags(&evA, cudaEventDisableTiming) != cudaSuccess ||
                cudaEventCreateWithFlags(&evB, cudaEventDisableTiming) != cudaSuccess ||
                cudaEventCreateWithFlags(&evC, cudaEventDisableTiming) != cudaSuccess ||
                cudaEventCreateWithFlags(&evD, cudaEventDisableTiming) != cudaSuccess) {
                s2 = nullptr;
            }
        }
    }

    cudaFuncSetAttribute(proj_mma_kernel, cudaFuncAttributeMaxDynamicSharedMemorySize,
                         PROJ_SMEM);
    cudaFuncSetAttribute(attn_kernel, cudaFuncAttributeMaxDynamicSharedMemorySize,
                         ATT_SMEM_BYTES);

    const int n4x = MTOT * CDIM / 4;
    convW_kernel<<<dim3((CDIM * CDIM / 4 + 255) / 256, 3), 256>>>(
        (const float4*)Wq, (const float4*)Wk, (const float4*)Wv, (uint2*)pwh);
    convX_kernel<<<(n4x + 511) / 512, 256>>>(
        (const float4*)x, (uint2*)pxh, n4x);

    if (s2) {
        proj_mma_kernel<<<dim3(6, MTOT / 128, 1), 256, PROJ_SMEM>>>(
            pxh, pwh, bq, bk, bv, 0);
        cudaEventRecord(evA, 0);
        cudaStreamWaitEvent(s2, evA, 0);
        proj_mma_kernel<<<dim3(6, MTOT / 128, 1), 256, PROJ_SMEM, s2>>>(
            pxh, pwh, bq, bk, bv, 2);
        cudaEventRecord(evB, s2);
        attn_kernel<<<dim3(256, BATCH), 256, ATT_SMEM_BYTES>>>(pQ, pK, pV, pO, 0);
        cudaEventRecord(evC, 0);
        cudaStreamWaitEvent(s2, evC, 0);
        transpose_kernel<<<dim3(NSEQ / 64, 8, BATCH), dim3(8, 32), 0, s2>>>(pO, out, 0);
        cudaEventRecord(evD, s2);
        cudaStreamWaitEvent(0, evB, 0);
        attn_kernel<<<dim3(256, BATCH), 256, ATT_SMEM_BYTES>>>(pQ, pK, pV, pO, 256);
        cudaStreamWaitEvent(0, evD, 0);
        transpose_kernel<<<dim3(NSEQ / 64, 8, BATCH), dim3(8, 32)>>>(pO, out, 8);
    } else {
        proj_mma_kernel<<<dim3(6, MTOT / 128, 1), 256, PROJ_SMEM>>>(
            pxh, pwh, bq, bk, bv, 0);
        proj_mma_kernel<<<dim3(6, MTOT / 128, 1), 256, PROJ_SMEM>>>(
            pxh, pwh, bq, bk, bv, 2);
        attn_kernel<<<dim3(256, BATCH), 256, ATT_SMEM_BYTES>>>(pQ, pK, pV, pO, 0);
        attn_kernel<<<dim3(256, BATCH), 256, ATT_SMEM_BYTES>>>(pQ, pK, pV, pO, 256);
        transpose_kernel<<<dim3(NSEQ / 64, 8, BATCH), dim3(8, 32)>>>(pO, out, 0);
        transpose_kernel<<<dim3(NSEQ / 64, 8, BATCH), dim3(8, 32)>>>(pO, out, 8);
    }
}

// round 17
// speedup vs baseline: 1.0756x; 1.0756x over previous
#include <cuda_runtime.h>
#include <cuda_fp16.h>
#include <math.h>
#include <stdint.h>

#define BATCH 16
#define NSEQ 4096
#define CDIM 512
#define MTOT (BATCH * NSEQ)
#define ELEMS ((size_t)BATCH * CDIM * NSEQ)

__device__ __half g_Qh[ELEMS];
__device__ __half g_Kh[ELEMS];
__device__ __half g_Vh[ELEMS];
__device__ __half g_Oh[ELEMS];

__device__ __half g_xh[(size_t)MTOT * CDIM];
__device__ __half g_wh[3 * CDIM * CDIM];

__device__ __forceinline__ uint32_t smem_u32(const void* p) {
    uint32_t a;
    asm("{ .reg .u64 t; cvta.to.shared.u64 t, %1; cvt.u32.u64 %0, t; }"
        : "=r"(a) : "l"(p));
    return a;
}

#define LDSM_X4(r0, r1, r2, r3, addr) \
    asm volatile("ldmatrix.sync.aligned.m8n8.x4.shared.b16 {%0,%1,%2,%3}, [%4];" \
        : "=r"(r0), "=r"(r1), "=r"(r2), "=r"(r3) : "r"(addr))

#define LDSM_X4T(r0, r1, r2, r3, addr) \
    asm volatile("ldmatrix.sync.aligned.m8n8.x4.trans.shared.b16 {%0,%1,%2,%3}, [%4];" \
        : "=r"(r0), "=r"(r1), "=r"(r2), "=r"(r3) : "r"(addr))

#define MMA_F16(c, a0, a1, a2, a3, b0, b1) \
    asm volatile("mma.sync.aligned.m16n8k16.row.col.f32.f16.f16.f32 " \
        "{%0,%1,%2,%3}, {%4,%5,%6,%7}, {%8,%9}, {%0,%1,%2,%3};" \
        : "+f"((c)[0]), "+f"((c)[1]), "+f"((c)[2]), "+f"((c)[3]) \
        : "r"(a0), "r"(a1), "r"(a2), "r"(a3), "r"(b0), "r"(b1))

#define CP_ASYNC16(dst, src) \
    asm volatile("cp.async.cg.shared.global [%0], [%1], 16;" \
        :: "r"(dst), "l"(src) : "memory")

// ---------------------------------------------------------------------------
// fp32 -> fp16 conversion kernels (convX takes an element offset for b-split)
// ---------------------------------------------------------------------------
__global__ __launch_bounds__(256) void convX_kernel(
    const float4* __restrict__ in, uint2* __restrict__ outp, int n4, int off4)
{
    int i = blockIdx.x * 512 + threadIdx.x + off4;
    #pragma unroll
    for (int r = 0; r < 2; ++r) {
        int idx = i + r * 256;
        if (idx < n4 + off4) {
            float4 v = in[idx];
            __half2 h0 = __floats2half2_rn(v.x, v.y);
            __half2 h1 = __floats2half2_rn(v.z, v.w);
            uint2 o;
            o.x = *(uint32_t*)&h0;
            o.y = *(uint32_t*)&h1;
            outp[idx] = o;
        }
    }
}

__global__ __launch_bounds__(256) void convW_kernel(
    const float4* __restrict__ Wq,
    const float4* __restrict__ Wk,
    const float4* __restrict__ Wv,
    uint2* __restrict__ outp)
{
    const int z = blockIdx.y;
    const float4* src = (z == 0) ? Wq : (z == 1) ? Wk : Wv;
    const int n4 = CDIM * CDIM / 4;
    int i = blockIdx.x * 256 + threadIdx.x;
    if (i >= n4) return;
    float4 v = src[i];
    __half2 h0 = __floats2half2_rn(v.x, v.y);
    __half2 h1 = __floats2half2_rn(v.z, v.w);
    uint2 o;
    o.x = *(uint32_t*)&h0;
    o.y = *(uint32_t*)&h1;
    outp[(size_t)z * n4 + i] = o;
}

// ---------------------------------------------------------------------------
// Projection GEMM via mma.sync (fp16, fp32 accum). R12 config (best known):
// K32 chunks, 4-stage cp.async, 2 CTA/SM, L2-friendly grid.
// Split by n-half via n_tile_base (batch-half pipeline).
// ---------------------------------------------------------------------------
#define PTS 40
#define PTILE_B (128 * PTS * 2)
#define PSTAGE_B (2 * PTILE_B)
#define PROJ_SMEM (4 * PSTAGE_B)

__global__ __launch_bounds__(256, 2) void proj_mma_kernel(
    const __half* __restrict__ xh,
    const __half* __restrict__ whp,
    const float* __restrict__ biasq,
    const float* __restrict__ biask,
    const float* __restrict__ biasv,
    int n_tile_base)
{
    extern __shared__ __half smem[];
    const uint32_t smb = smem_u32(smem);

    const int tid  = threadIdx.x;
    const int lane = tid & 31;
    const int warp = tid >> 5;
    const int wm   = warp >> 2;
    const int wn   = warp & 3;

    const int bx = blockIdx.x;              // 0..11 (z * 4 + d-tile)
    const int z  = bx >> 2;
    const int d0 = (bx & 3) * 128;
    const int n0 = (blockIdx.y + n_tile_base) * 128;

    const __half* W = whp + (size_t)z * CDIM * CDIM;

    float acc[4][4][4];
    #pragma unroll
    for (int i = 0; i < 4; ++i)
        #pragma unroll
        for (int j = 0; j < 4; ++j)
            #pragma unroll
            for (int q = 0; q < 4; ++q) acc[i][j][q] = 0.f;

    const int lr = tid >> 1;
    const int lc = (tid & 1) * 16;

    #define LOAD_STAGE(s, k0) do { \
        const uint32_t db = smb + (s) * PSTAGE_B + (uint32_t)(lr * PTS + lc) * 2; \
        const size_t go = (size_t)lr * 512 + (k0) + lc; \
        CP_ASYNC16(db,                W + (size_t)d0 * 512 + go); \
        CP_ASYNC16(db + 16,           W + (size_t)d0 * 512 + go + 8); \
        CP_ASYNC16(db + PTILE_B,      xh + (size_t)n0 * 512 + go); \
        CP_ASYNC16(db + PTILE_B + 16, xh + (size_t)n0 * 512 + go + 8); \
    } while (0)

    LOAD_STAGE(0, 0);
    asm volatile("cp.async.commit_group;" ::: "memory");
    LOAD_STAGE(1, 32);
    asm volatile("cp.async.commit_group;" ::: "memory");
    LOAD_STAGE(2, 64);
    asm volatile("cp.async.commit_group;" ::: "memory");

    const int aRow  = wm * 64 + (lane & 15);
    const int aCol  = (lane >> 4) * 8;
    const int g     = lane >> 3;
    const int bRow  = wn * 32 + (g & 2) * 4 + (lane & 7);
    const int bElem = (g & 1) * 8;

    for (int kt = 0; kt < 16; ++kt) {
        asm volatile("cp.async.wait_group 2;" ::: "memory");
        __syncthreads();

        if (kt < 13) LOAD_STAGE((kt + 3) & 3, (kt + 3) * 32);
        asm volatile("cp.async.commit_group;" ::: "memory");

        const uint32_t sA = smb + (kt & 3) * PSTAGE_B;
        const uint32_t sB = sA + PTILE_B;

        #pragma unroll
        for (int kk = 0; kk < 2; ++kk) {
            uint32_t bh[4][2];
            #pragma unroll
            for (int p = 0; p < 2; ++p) {
                uint32_t ba = sB + (uint32_t)((bRow + p * 16) * PTS + kk * 16 + bElem) * 2;
                LDSM_X4(bh[2 * p][0], bh[2 * p][1], bh[2 * p + 1][0], bh[2 * p + 1][1], ba);
            }
            #pragma unroll
            for (int mi = 0; mi < 4; ++mi) {
                uint32_t aa = sA + (uint32_t)((aRow + mi * 16) * PTS + kk * 16 + aCol) * 2;
                uint32_t a0, a1, a2, a3;
                LDSM_X4(a0, a1, a2, a3, aa);
                #pragma unroll
                for (int ni = 0; ni < 4; ++ni)
                    MMA_F16(acc[mi][ni], a0, a1, a2, a3, bh[ni][0], bh[ni][1]);
            }
        }
    }

    const float* bias = (z == 0) ? biasq : (z == 1) ? biask : biasv;
    __half* outp = (z == 0) ? g_Qh : (z == 1) ? g_Kh : g_Vh;
    const int b  = n0 >> 12;
    const int nb = (n0 & 4095) + wn * 32 + (lane & 3) * 2;

    #pragma unroll
    for (int mi = 0; mi < 4; ++mi) {
        const int dA = d0 + wm * 64 + mi * 16 + (lane >> 2);
        const float bA = bias[dA];
        const float bB = bias[dA + 8];
        __half* rowA = outp + (((size_t)(b * 512 + dA)) << 12) + nb;
        __half* rowB = rowA + ((size_t)8 << 12);
        #pragma unroll
        for (int ni = 0; ni < 4; ++ni) {
            float s0 = 1.f / (1.f + __expf(-(acc[mi][ni][0] + bA)));
            float s1 = 1.f / (1.f + __expf(-(acc[mi][ni][1] + bA)));
            float s2 = 1.f / (1.f + __expf(-(acc[mi][ni][2] + bB)));
            float s3 = 1.f / (1.f + __expf(-(acc[mi][ni][3] + bB)));
            *(__half2*)(rowA + ni * 8) = __floats2half2_rn(s0, s1);
            *(__half2*)(rowB + ni * 8) = __floats2half2_rn(s2, s3);
        }
    }
}

// ---------------------------------------------------------------------------
// Attention via fp16 tensor cores. Aliased smem (55296 B, 4 CTA/SM).
// Split by batch-half via b_base.
// ---------------------------------------------------------------------------
#define SH72 72
#define SH40 40
#define SF36 36
#define SF68 68

#define OFF_HQ   0
#define OFF_HK   9216
#define OFF_HV   18432
#define OFF_Hq   27648
#define OFF_Hk   32256
#define OFF_HQK  27648
#define OFF_HKQ  32768
#define OFF_S1   37376
#define OFF_S2   46592
#define OFF_HKQV 37376
#define ATT_SMEM_BYTES 55296

__global__ __launch_bounds__(256) void attn_kernel(
    const __half* __restrict__ gQ,
    const __half* __restrict__ gK,
    const __half* __restrict__ gV,
    __half* __restrict__ gO,
    int b_base)
{
    extern __shared__ char sm8[];
    const uint32_t sb = smem_u32(sm8);
    __half* hQ   = (__half*)(sm8 + OFF_HQ);
    __half* hK   = (__half*)(sm8 + OFF_HK);
    __half* hq   = (__half*)(sm8 + OFF_Hq);
    __half* hk   = (__half*)(sm8 + OFF_Hk);
    __half* hQk  = (__half*)(sm8 + OFF_HQK);
    __half* hKq  = (__half*)(sm8 + OFF_HKQ);
    __half* hKqv = (__half*)(sm8 + OFF_HKQV);
    float*  sS1  = (float*)(sm8 + OFF_S1);
    float*  sS2  = (float*)(sm8 + OFF_S2);

    const int bc = (blockIdx.y + b_base) * 512 + blockIdx.x;
    const size_t base = (size_t)bc * 4096;
    const int tid  = threadIdx.x;
    const int lane = tid & 31;
    const int warp = tid >> 5;

    #pragma unroll
    for (int it = 0; it < 6; ++it) {
        int idx = tid + it * 256;
        int m    = idx >> 9;
        int rest = idx & 511;
        int r    = rest >> 3;
        int c8   = (rest & 7) * 8;
        const __half* src = (m == 0) ? gQ : (m == 1) ? gK : gV;
        uint4 v = *(const uint4*)(src + base + (r << 6) + c8);
        __half* dst = (__half*)(sm8 + (m == 0 ? OFF_HQ : m == 1 ? OFF_HK : OFF_HV)) + r * SH72 + c8;
        *(uint4*)dst = v;
    }
    __syncthreads();

    {
        const __half2 hhalf = __float2half2_rn(0.5f);
        #pragma unroll
        for (int it = 0; it < 8; ++it) {
            int idx = tid + it * 256;
            int which = idx >> 10;
            int i  = (idx >> 5) & 31;
            int cc = (idx & 31) * 2;
            const __half* s = which ? hK : hQ;
            __half* d      = which ? hk : hq;
            __half2 a = *(const __half2*)(s + (2 * i) * SH72 + cc);
            __half2 b = *(const __half2*)(s + (2 * i + 1) * SH72 + cc);
            *(__half2*)(d + i * SH72 + cc) = __hmul2(__hadd2(a, b), hhalf);
        }
    }
    __syncthreads();

    const float scale = 0.044194173824159216f;
    const int aRow = lane & 15;
    const int aCol = (lane >> 4) * 8;
    const int g    = lane >> 3;
    const int bR   = (g & 2) * 4 + (lane & 7);
    const int bE   = (g & 1) * 8;
    const int tR   = (g & 1) * 8 + (lane & 7);
    const int tC   = (g >> 1) * 8;
    const int cr   = lane >> 2;
    const int ccol = (lane & 3) * 2;

    {
        const int wm = warp >> 1, wn = warp & 1;
        float acc[2][4] = {{0,0,0,0},{0,0,0,0}};
        #pragma unroll
        for (int ks = 0; ks < 4; ++ks) {
            uint32_t a0,a1,a2,a3,b0,b1,b2,b3;
            LDSM_X4(a0,a1,a2,a3, sb + OFF_HQ + (uint32_t)((wm*16 + aRow)*SH72 + ks*16 + aCol)*2);
            LDSM_X4(b0,b1,b2,b3, sb + OFF_Hk + (uint32_t)((wn*16 + bR)*SH72 + ks*16 + bE)*2);
            MMA_F16(acc[0], a0,a1,a2,a3, b0,b1);
            MMA_F16(acc[1], a0,a1,a2,a3, b2,b3);
        }
        #pragma unroll
        for (int nt = 0; nt < 2; ++nt) {
            float* p0 = sS1 + (wm*16 + cr) * SF36 + wn*16 + nt*8 + ccol;
            float* p1 = p0 + 8 * SF36;
            *(float2*)p0 = make_float2(acc[nt][0]*scale, acc[nt][1]*scale);
            *(float2*)p1 = make_float2(acc[nt][2]*scale, acc[nt][3]*scale);
        }
    }

    {
        const int wm = warp >> 2, wn = warp & 3;
        float acc[2][4] = {{0,0,0,0},{0,0,0,0}};
        #pragma unroll
        for (int ks = 0; ks < 4; ++ks) {
            uint32_t a0,a1,a2,a3,b0,b1,b2,b3;
            LDSM_X4(a0,a1,a2,a3, sb + OFF_Hq + (uint32_t)((wm*16 + aRow)*SH72 + ks*16 + aCol)*2);
            LDSM_X4(b0,b1,b2,b3, sb + OFF_HK + (uint32_t)((wn*16 + bR)*SH72 + ks*16 + bE)*2);
            MMA_F16(acc[0], a0,a1,a2,a3, b0,b1);
            MMA_F16(acc[1], a0,a1,a2,a3, b2,b3);
        }
        #pragma unroll
        for (int nt = 0; nt < 2; ++nt) {
            float* p0 = sS2 + (wm*16 + cr) * SF68 + wn*16 + nt*8 + ccol;
            float* p1 = p0 + 8 * SF68;
            *(float2*)p0 = make_float2(acc[nt][0]*scale, acc[nt][1]*scale);
            *(float2*)p1 = make_float2(acc[nt][2]*scale, acc[nt][3]*scale);
        }
    }
    __syncthreads();

    {
        const int row = tid >> 2;
        const int s   = tid & 3;
        float* rp = sS1 + row * SF36 + s * 8;
        float4 v0 = *(float4*)rp;
        float4 v1 = *(float4*)(rp + 4);
        float m = fmaxf(fmaxf(fmaxf(v0.x, v0.y), fmaxf(v0.z, v0.w)),
                        fmaxf(fmaxf(v1.x, v1.y), fmaxf(v1.z, v1.w)));
        m = fmaxf(m, __shfl_xor_sync(0xffffffffu, m, 1));
        m = fmaxf(m, __shfl_xor_sync(0xffffffffu, m, 2));
        v0.x = __expf(v0.x - m); v0.y = __expf(v0.y - m);
        v0.z = __expf(v0.z - m); v0.w = __expf(v0.w - m);
        v1.x = __expf(v1.x - m); v1.y = __expf(v1.y - m);
        v1.z = __expf(v1.z - m); v1.w = __expf(v1.w - m);
        float su = v0.x + v0.y + v0.z + v0.w + v1.x + v1.y + v1.z + v1.w;
        su += __shfl_xor_sync(0xffffffffu, su, 1);
        su += __shfl_xor_sync(0xffffffffu, su, 2);
        float inv = 1.f / su;
        __half* wp = hQk + row * SH40 + s * 8;
        *(__half2*)(wp)     = __floats2half2_rn(v0.x * inv, v0.y * inv);
        *(__half2*)(wp + 2) = __floats2half2_rn(v0.z * inv, v0.w * inv);
        *(__half2*)(wp + 4) = __floats2half2_rn(v1.x * inv, v1.y * inv);
        *(__half2*)(wp + 6) = __floats2half2_rn(v1.z * inv, v1.w * inv);
    }

    {
        const int row = tid >> 3;
        const int s   = tid & 7;
        float* rp = sS2 + row * SF68 + s * 8;
        float4 v0 = *(float4*)rp;
        float4 v1 = *(float4*)(rp + 4);
        float m = fmaxf(fmaxf(fmaxf(v0.x, v0.y), fmaxf(v0.z, v0.w)),
                        fmaxf(fmaxf(v1.x, v1.y), fmaxf(v1.z, v1.w)));
        m = fmaxf(m, __shfl_xor_sync(0xffffffffu, m, 1));
        m = fmaxf(m, __shfl_xor_sync(0xffffffffu, m, 2));
        m = fmaxf(m, __shfl_xor_sync(0xffffffffu, m, 4));
        v0.x = __expf(v0.x - m); v0.y = __expf(v0.y - m);
        v0.z = __expf(v0.z - m); v0.w = __expf(v0.w - m);
        v1.x = __expf(v1.x - m); v1.y = __expf(v1.y - m);
        v1.z = __expf(v1.z - m); v1.w = __expf(v1.w - m);
        float su = v0.x + v0.y + v0.z + v0.w + v1.x + v1.y + v1.z + v1.w;
        su += __shfl_xor_sync(0xffffffffu, su, 1);
        su += __shfl_xor_sync(0xffffffffu, su, 2);
        su += __shfl_xor_sync(0xffffffffu, su, 4);
        float inv = 1.f / su;
        __half* wp = hKq + row * SH72 + s * 8;
        *(__half2*)(wp)     = __floats2half2_rn(v0.x * inv, v0.y * inv);
        *(__half2*)(wp + 2) = __floats2half2_rn(v0.z * inv, v0.w * inv);
        *(__half2*)(wp + 4) = __floats2half2_rn(v1.x * inv, v1.y * inv);
        *(__half2*)(wp + 6) = __floats2half2_rn(v1.z * inv, v1.w * inv);
    }
    __syncthreads();

    {
        const int wm = warp >> 2, wn = warp & 3;
        float acc[2][4] = {{0,0,0,0},{0,0,0,0}};
        #pragma unroll
        for (int ks = 0; ks < 4; ++ks) {
            uint32_t a0,a1,a2,a3,b0,b1,b2,b3;
            LDSM_X4(a0,a1,a2,a3, sb + OFF_HKQ + (uint32_t)((wm*16 + aRow)*SH72 + ks*16 + aCol)*2);
            LDSM_X4T(b0,b1,b2,b3, sb + OFF_HV + (uint32_t)((ks*16 + tR)*SH72 + wn*16 + tC)*2);
            MMA_F16(acc[0], a0,a1,a2,a3, b0,b1);
            MMA_F16(acc[1], a0,a1,a2,a3, b2,b3);
        }
        #pragma unroll
        for (int nt = 0; nt < 2; ++nt) {
            __half* p0 = hKqv + (wm*16 + cr) * SH72 + wn*16 + nt*8 + ccol;
            __half* p1 = p0 + 8 * SH72;
            *(__half2*)p0 = __floats2half2_rn(acc[nt][0], acc[nt][1]);
            *(__half2*)p1 = __floats2half2_rn(acc[nt][2], acc[nt][3]);
        }
    }
    __syncthreads();

    {
        const int wm = warp >> 1, wn = warp & 1;
        float acc[4][4];
        #pragma unroll
        for (int i = 0; i < 4; ++i)
            #pragma unroll
            for (int q = 0; q < 4; ++q) acc[i][q] = 0.f;
        #pragma unroll
        for (int ks = 0; ks < 2; ++ks) {
            uint32_t a0,a1,a2,a3;
            LDSM_X4(a0,a1,a2,a3, sb + OFF_HQK + (uint32_t)((wm*16 + aRow)*SH40 + ks*16 + aCol)*2);
            #pragma unroll
            for (int nh = 0; nh < 2; ++nh) {
                uint32_t b0,b1,b2,b3;
                LDSM_X4T(b0,b1,b2,b3,
                    sb + OFF_HKQV + (uint32_t)((ks*16 + tR)*SH72 + wn*32 + nh*16 + tC)*2);
                MMA_F16(acc[nh*2+0], a0,a1,a2,a3, b0,b1);
                MMA_F16(acc[nh*2+1], a0,a1,a2,a3, b2,b3);
            }
        }
        #pragma unroll
        for (int nt = 0; nt < 4; ++nt) {
            __half* p0 = gO + base + (wm*16 + cr) * 64 + wn*32 + nt*8 + ccol;
            __half* p1 = p0 + 8 * 64;
            *(__half2*)p0 = __floats2half2_rn(acc[nt][0], acc[nt][1]);
            *(__half2*)p1 = __floats2half2_rn(acc[nt][2], acc[nt][3]);
        }
    }
}

// ---------------------------------------------------------------------------
// Transpose [B][C][N] fp16 -> [B][N][C] fp32, split by batch-half (b_base).
// ---------------------------------------------------------------------------
__global__ __launch_bounds__(256) void transpose_kernel(
    const __half* __restrict__ gO, float* __restrict__ out, int b_base)
{
    __shared__ float tile[64][33];
    const int b  = blockIdx.z + b_base;
    const int n0 = blockIdx.x * 64;
    const int c0 = blockIdx.y * 32;
    const int tx = threadIdx.x;
    const int ty = threadIdx.y;
    const int tid = ty * 8 + tx;

    const __half* src = gO + ((size_t)b * 512 + c0 + ty) * 4096 + n0 + tx * 8;
    uint4 v = *(const uint4*)src;
    const __half* hv = (const __half*)&v;
    #pragma unroll
    for (int e = 0; e < 8; ++e)
        tile[tx * 8 + e][ty] = __half2float(hv[e]);
    __syncthreads();

    float* dst = out + ((size_t)b * 4096) * 512;
    #pragma unroll
    for (int k = 0; k < 8; ++k) {
        int lin = tid + k * 256;
        int n = lin >> 5;
        int c = lin & 31;
        dst[(size_t)(n0 + n) * 512 + c0 + c] = tile[n][c];
    }
}

// ---------------------------------------------------------------------------
// Host side — batch-half pipeline:
//   main: convW, convX0, proj0, attn0, [wait p1] attn1, [wait t0] transp1
//   s2:   convX1, [wait cw+p0] proj1, [wait a0] transp0
// ---------------------------------------------------------------------------
extern "C" void kernel_launch(void* const* d_in, const int* in_sizes, int n_in,
                              void* d_out, int out_size)
{
    (void)in_sizes; (void)n_in; (void)out_size;
    const float* x  = (const float*)d_in[0];
    const float* Wq = (const float*)d_in[1];
    const float* bq = (const float*)d_in[2];
    const float* Wk = (const float*)d_in[3];
    const float* bk = (const float*)d_in[4];
    const float* Wv = (const float*)d_in[5];
    const float* bv = (const float*)d_in[6];
    float* out = (float*)d_out;

    __half *pQ, *pK, *pV, *pO, *pxh, *pwh;
    cudaGetSymbolAddress((void**)&pQ, g_Qh);
    cudaGetSymbolAddress((void**)&pK, g_Kh);
    cudaGetSymbolAddress((void**)&pV, g_Vh);
    cudaGetSymbolAddress((void**)&pO, g_Oh);
    cudaGetSymbolAddress((void**)&pxh, g_xh);
    cudaGetSymbolAddress((void**)&pwh, g_wh);

    static cudaStream_t s2 = nullptr;
    static cudaEvent_t evX1 = nullptr, evP0 = nullptr, evP1 = nullptr,
                       evA0 = nullptr, evT0 = nullptr;
    static bool tried = false;
    if (!tried) {
        tried = true;
        if (cudaStreamCreateWithFlags(&s2, cudaStreamNonBlocking) != cudaSuccess)
            s2 = nullptr;
        if (s2) {
            if (cudaEventCreateWithFlags(&evX1, cudaEventDisableTiming) != cudaSuccess ||
                cudaEventCreateWithFlags(&evP0, cudaEventDisableTiming) != cudaSuccess ||
                cudaEventCreateWithFlags(&evP1, cudaEventDisableTiming) != cudaSuccess ||
                cudaEventCreateWithFlags(&evA0, cudaEventDisableTiming) != cudaSuccess ||
                cudaEventCreateWithFlags(&evT0, cudaEventDisableTiming) != cudaSuccess) {
                s2 = nullptr;
            }
        }
    }

    cudaFuncSetAttribute(proj_mma_kernel, cudaFuncAttributeMaxDynamicSharedMemorySize,
                         PROJ_SMEM);
    cudaFuncSetAttribute(attn_kernel, cudaFuncAttributeMaxDynamicSharedMemorySize,
                         ATT_SMEM_BYTES);

    const int n4h = MTOT * CDIM / 8;      // float4 elements per batch-half

    if (s2) {
        // side stream: convert x half 1 early (independent)
        convX_kernel<<<(n4h + 511) / 512, 256, 0, s2>>>(
            (const float4*)x, (uint2*)pxh, n4h, n4h);
        cudaEventRecord(evX1, s2);

        // main: weights + x half 0 + proj half 0
        convW_kernel<<<dim3((CDIM * CDIM / 4 + 255) / 256, 3), 256>>>(
            (const float4*)Wq, (const float4*)Wk, (const float4*)Wv, (uint2*)pwh);
        convX_kernel<<<(n4h + 511) / 512, 256>>>(
            (const float4*)x, (uint2*)pxh, n4h, 0);
        proj_mma_kernel<<<dim3(12, 256, 1), 256, PROJ_SMEM>>>(
            pxh, pwh, bq, bk, bv, 0);
        cudaEventRecord(evP0, 0);

        // side: proj half 1 (needs convW+proj0 ordering via evP0, convX1 in-stream)
        cudaStreamWaitEvent(s2, evP0, 0);
        proj_mma_kernel<<<dim3(12, 256, 1), 256, PROJ_SMEM, s2>>>(
            pxh, pwh, bq, bk, bv, 256);
        cudaEventRecord(evP1, s2);

        // main: attn half 0 overlaps proj half 1
        attn_kernel<<<dim3(512, 8), 256, ATT_SMEM_BYTES>>>(pQ, pK, pV, pO, 0);
        cudaEventRecord(evA0, 0);

        // side: transpose half 0 after proj1+attn0
        cudaStreamWaitEvent(s2, evA0, 0);
        transpose_kernel<<<dim3(NSEQ / 64, 16, 8), dim3(8, 32), 0, s2>>>(pO, out, 0);
        cudaEventRecord(evT0, s2);

        // main: attn half 1 (needs proj1), then transpose half 1; join
        cudaStreamWaitEvent(0, evP1, 0);
        attn_kernel<<<dim3(512, 8), 256, ATT_SMEM_BYTES>>>(pQ, pK, pV, pO, 8);
        cudaStreamWaitEvent(0, evT0, 0);
        transpose_kernel<<<dim3(NSEQ / 64, 16, 8), dim3(8, 32)>>>(pO, out, 8);
    } else {
        convW_kernel<<<dim3((CDIM * CDIM / 4 + 255) / 256, 3), 256>>>(
            (const float4*)Wq, (const float4*)Wk, (const float4*)Wv, (uint2*)pwh);
        convX_kernel<<<(n4h + 511) / 512, 256>>>(
            (const float4*)x, (uint2*)pxh, n4h, 0);
        convX_kernel<<<(n4h + 511) / 512, 256>>>(
            (const float4*)x, (uint2*)pxh, n4h, n4h);
        proj_mma_kernel<<<dim3(12, 256, 1), 256, PROJ_SMEM>>>(
            pxh, pwh, bq, bk, bv, 0);
        proj_mma_kernel<<<dim3(12, 256, 1), 256, PROJ_SMEM>>>(
            pxh, pwh, bq, bk, bv, 256);
        attn_kernel<<<dim3(512, 8), 256, ATT_SMEM_BYTES>>>(pQ, pK, pV, pO, 0);
        attn_kernel<<<dim3(512, 8), 256, ATT_SMEM_BYTES>>>(pQ, pK, pV, pO, 8);
        transpose_kernel<<<dim3(NSEQ / 64, 16, 8), dim3(8, 32)>>>(pO, out, 0);
        transpose_kernel<<<dim3(NSEQ / 64, 16, 8), dim3(8, 32)>>>(pO, out, 8);
    }
}